// round 1
// baseline (speedup 1.0000x reference)
#include <cuda_runtime.h>
#include <math.h>

// Problem shape (fixed by the dataset): predict (8,19,512,512) f32, target (8,512,512) i32
#define NPIX   (8 * 512 * 512)   // 2,097,152 pixels
#define HWSZ   (512 * 512)       // 262,144 per (n, c) plane
#define CCH    19                // classes
#define NBIN1  2048              // top-11-bit histogram (covers bits up to 2.0f sentinel)
#define NBIN2  2048              // middle-11-bit
#define NBIN3  1024              // low-10-bit

#define OHEM_THRESH 0.7f

// ---- device scratch (no allocations allowed) ----
__device__ float        g_prob[NPIX];     // 8 MB: softmax prob of target class (2.0f sentinel for ignored)
__device__ unsigned int g_hist[NBIN1];
__device__ int          g_nvalid;
__device__ unsigned int g_prefix;         // radix-select prefix (grows 11 -> 22 bits)
__device__ int          g_k;              // remaining rank within current prefix
__device__ float        g_threshold;
__device__ double       g_sum;
__device__ int          g_cnt;

// ------------------------------------------------------------------
__global__ void k_init() {
    int i = blockIdx.x * blockDim.x + threadIdx.x;
    if (i < NBIN1) g_hist[i] = 0u;
    if (i == 0) { g_nvalid = 0; g_sum = 0.0; g_cnt = 0; }
}

// Pass A: per-pixel online log-softmax + gather; store prob; build top-11-bit histogram; count valid.
__global__ void k_compute(const float* __restrict__ predict,
                          const int*   __restrict__ target, int N) {
    __shared__ unsigned int sh[NBIN1];
    for (int i = threadIdx.x; i < NBIN1; i += blockDim.x) sh[i] = 0u;
    __syncthreads();

    int lv = 0;
    for (int i = blockIdx.x * blockDim.x + threadIdx.x; i < N;
         i += gridDim.x * blockDim.x) {
        int t = target[i];
        float p;
        if (t < 0) {
            p = 2.0f;  // sentinel: sorts after every real prob (reference uses 2.0)
        } else {
            int n  = i / HWSZ;
            int hw = i - n * HWSZ;
            const float* base = predict + (size_t)n * CCH * HWSZ + hw;
            float m = -1e30f, s = 0.0f, xt = 0.0f;
            #pragma unroll
            for (int c = 0; c < CCH; c++) {
                float x = __ldg(base + (size_t)c * HWSZ);
                if (c == t) xt = x;
                float mn = fmaxf(m, x);
                s = s * __expf(m - mn) + __expf(x - mn);
                m = mn;
            }
            float lp = xt - (m + __logf(s));   // log-softmax at target class
            p = __expf(lp);
            lv++;
        }
        g_prob[i] = p;
        atomicAdd(&sh[__float_as_uint(p) >> 21], 1u);
    }
    __syncthreads();
    for (int i = threadIdx.x; i < NBIN1; i += blockDim.x) {
        unsigned v = sh[i];
        if (v) atomicAdd(&g_hist[i], v);
    }
    #pragma unroll
    for (int off = 16; off; off >>= 1) lv += __shfl_down_sync(0xffffffffu, lv, off);
    if ((threadIdx.x & 31) == 0 && lv) atomicAdd(&g_nvalid, lv);
}

// Radix-select scan 1: choose top-11-bit bucket containing rank k; reset hist.
__global__ void k_scan1(const int* __restrict__ min_kept) {
    if (threadIdx.x == 0) {
        long long nv = (long long)g_nvalid;
        long long k  = (long long)(*min_kept);
        if (nv - 1 < k) k = nv - 1;
        if (k < 0) k = 0;
        long long cum = 0; unsigned b = 0;
        for (unsigned i = 0; i < NBIN1; i++) {
            unsigned h = g_hist[i];
            if (cum + (long long)h > k) { b = i; k -= cum; break; }
            cum += h;
        }
        g_prefix = b;
        g_k = (int)k;
    }
    __syncthreads();
    for (int i = threadIdx.x; i < NBIN1; i += blockDim.x) g_hist[i] = 0u;
}

__global__ void k_pass2(int N) {
    __shared__ unsigned int sh[NBIN2];
    for (int i = threadIdx.x; i < NBIN2; i += blockDim.x) sh[i] = 0u;
    __syncthreads();
    unsigned pref = g_prefix;
    for (int i = blockIdx.x * blockDim.x + threadIdx.x; i < N;
         i += gridDim.x * blockDim.x) {
        unsigned b = __float_as_uint(g_prob[i]);
        if ((b >> 21) == pref) atomicAdd(&sh[(b >> 10) & (NBIN2 - 1)], 1u);
    }
    __syncthreads();
    for (int i = threadIdx.x; i < NBIN2; i += blockDim.x) {
        unsigned v = sh[i];
        if (v) atomicAdd(&g_hist[i], v);
    }
}

__global__ void k_scan2() {
    if (threadIdx.x == 0) {
        long long k = (long long)g_k;
        long long cum = 0; unsigned b = 0;
        for (unsigned i = 0; i < NBIN2; i++) {
            unsigned h = g_hist[i];
            if (cum + (long long)h > k) { b = i; k -= cum; break; }
            cum += h;
        }
        g_prefix = (g_prefix << 11) | b;   // now top 22 bits
        g_k = (int)k;
    }
    __syncthreads();
    for (int i = threadIdx.x; i < NBIN1; i += blockDim.x) g_hist[i] = 0u;
}

__global__ void k_pass3(int N) {
    __shared__ unsigned int sh[NBIN3];
    for (int i = threadIdx.x; i < NBIN3; i += blockDim.x) sh[i] = 0u;
    __syncthreads();
    unsigned pref = g_prefix;
    for (int i = blockIdx.x * blockDim.x + threadIdx.x; i < N;
         i += gridDim.x * blockDim.x) {
        unsigned b = __float_as_uint(g_prob[i]);
        if ((b >> 10) == pref) atomicAdd(&sh[b & (NBIN3 - 1)], 1u);
    }
    __syncthreads();
    for (int i = threadIdx.x; i < NBIN3; i += blockDim.x) {
        unsigned v = sh[i];
        if (v) atomicAdd(&g_hist[i], v);
    }
}

__global__ void k_scan3() {
    if (threadIdx.x == 0) {
        long long k = (long long)g_k;
        long long cum = 0; unsigned b = 0;
        for (unsigned i = 0; i < NBIN3; i++) {
            unsigned h = g_hist[i];
            if (cum + (long long)h > k) { b = i; break; }
            cum += h;
        }
        unsigned kth_bits = (g_prefix << 10) | b;   // exact bit pattern of k-th smallest
        g_threshold = fmaxf(__uint_as_float(kth_bits), OHEM_THRESH);
    }
}

// Final reduction: sum of -log(prob) where prob < threshold (sentinels 2.0 auto-excluded).
__global__ void k_reduce(int N) {
    float th = g_threshold;
    double s = 0.0;
    int    c = 0;
    for (int i = blockIdx.x * blockDim.x + threadIdx.x; i < N;
         i += gridDim.x * blockDim.x) {
        float p = g_prob[i];
        if (p < th) { s += (double)(-logf(p)); c++; }
    }
    #pragma unroll
    for (int off = 16; off; off >>= 1) {
        s += __shfl_down_sync(0xffffffffu, s, off);
        c += __shfl_down_sync(0xffffffffu, c, off);
    }
    __shared__ double ws[8];
    __shared__ int    wc[8];
    int warp = threadIdx.x >> 5;
    if ((threadIdx.x & 31) == 0) { ws[warp] = s; wc[warp] = c; }
    __syncthreads();
    if (threadIdx.x == 0) {
        double S = 0.0; int C2 = 0;
        int nw = (blockDim.x + 31) >> 5;
        for (int w = 0; w < nw; w++) { S += ws[w]; C2 += wc[w]; }
        if (C2 || S != 0.0) { atomicAdd(&g_sum, S); atomicAdd(&g_cnt, C2); }
    }
}

__global__ void k_final(float* out) {
    int c = g_cnt;
    if (c < 1) c = 1;
    out[0] = (float)(g_sum / (double)c);
}

// ------------------------------------------------------------------
extern "C" void kernel_launch(void* const* d_in, const int* in_sizes, int n_in,
                              void* d_out, int out_size) {
    const float* predict  = (const float*)d_in[0];
    const int*   target   = (const int*)d_in[1];
    const int*   min_kept = (const int*)d_in[2];
    float*       out      = (float*)d_out;

    int N = in_sizes[1];          // 2,097,152 pixels
    const int THREADS = 256;
    int grid = 148 * 8;           // grid-stride, ~7 pixels/thread
    if (grid > (N + THREADS - 1) / THREADS) grid = (N + THREADS - 1) / THREADS;

    k_init   <<<(NBIN1 + THREADS - 1) / THREADS, THREADS>>>();
    k_compute<<<grid, THREADS>>>(predict, target, N);
    k_scan1  <<<1, THREADS>>>(min_kept);
    k_pass2  <<<grid, THREADS>>>(N);
    k_scan2  <<<1, THREADS>>>();
    k_pass3  <<<grid, THREADS>>>(N);
    k_scan3  <<<1, THREADS>>>();
    k_reduce <<<grid, THREADS>>>(N);
    k_final  <<<1, 1>>>(out);
}

// round 2
// speedup vs baseline: 2.3410x; 2.3410x over previous
#include <cuda_runtime.h>
#include <math.h>

// predict (8,19,512,512) f32, target (8,512,512) i32, min_kept (1) i32 -> scalar f32
#define NPIX   (8 * 512 * 512)
#define HWSZ   (512 * 512)
#define CCH    19
#define NB     2048
#define T7BITS 0x3F333333u      // bits of 0.7f

// ---------------- device scratch ----------------
__device__ float        g_prob[NPIX];     // softmax prob of target class (2.0f sentinel)
__device__ unsigned int g_cand[NPIX];     // candidate bit patterns (uncertainty band)
__device__ unsigned int g_hist[NB];
__device__ int          g_nvalid, g_ncand, g_cnt, g_cntlow;
__device__ double       g_sum;
__device__ unsigned int g_blo, g_tmax, g_thresh, g_b2;
__device__ int          g_kprime, g_k3, g_band;

// ---------------------------------------------------------------
__global__ void k_init() {
    for (int i = threadIdx.x; i < NB; i += blockDim.x) g_hist[i] = 0u;
    if (threadIdx.x == 0) {
        g_nvalid = 0; g_ncand = 0; g_cnt = 0; g_cntlow = 0;
        g_sum = 0.0; g_band = 0; g_thresh = T7BITS; g_b2 = 0xFFFFFFFFu;
    }
}

// scalar helper for tail pixels
__device__ void scalar_pixel(const float* __restrict__ predict,
                             const int* __restrict__ target, int i,
                             unsigned* sh, int& lv, int& lc, double& ls) {
    int t = target[i];
    float p;
    if (t < 0) p = 2.0f;
    else {
        int n = i / HWSZ, hw = i - n * HWSZ;
        const float* base = predict + (size_t)n * CCH * HWSZ + hw;
        float m = -1e30f;
        for (int c = 0; c < CCH; c++) m = fmaxf(m, __ldg(base + (size_t)c * HWSZ));
        float s = 0.0f, xt = 0.0f;
        for (int c = 0; c < CCH; c++) {
            float x = __ldg(base + (size_t)c * HWSZ);
            s += __expf(x - m);
            if (c == t) xt = x;
        }
        float lp = xt - m - __logf(s);
        p = __expf(lp);
        lv++;
        if (p < 0.7f) { ls += -(double)lp; lc++; }
    }
    g_prob[i] = p;
    atomicAdd(&sh[__float_as_uint(p) >> 21], 1u);
}

// Pass A: softmax prob + histogram + valid count + sure-selected (p<0.7) sum.
__global__ void __launch_bounds__(256, 2)
k_compute(const float* __restrict__ predict, const int* __restrict__ target, int N) {
    __shared__ unsigned sh[NB];
    for (int i = threadIdx.x; i < NB; i += 256) sh[i] = 0u;
    __syncthreads();

    int N4 = N >> 2;
    int idx = blockIdx.x * 256 + threadIdx.x;
    int lv = 0, lc = 0;
    double ls = 0.0;

    if (idx < N4) {
        int i = idx << 2;
        int n = i / HWSZ, hw = i - n * HWSZ;
        const float4* base = (const float4*)(predict + (size_t)n * CCH * HWSZ + hw);
        float4 v[CCH];
        #pragma unroll
        for (int c = 0; c < CCH; c++) v[c] = __ldg(base + (size_t)c * (HWSZ / 4));
        int4 t = *(const int4*)(target + i);

        float4 m = v[0];
        #pragma unroll
        for (int c = 1; c < CCH; c++) {
            m.x = fmaxf(m.x, v[c].x); m.y = fmaxf(m.y, v[c].y);
            m.z = fmaxf(m.z, v[c].z); m.w = fmaxf(m.w, v[c].w);
        }
        float4 s = make_float4(0.f, 0.f, 0.f, 0.f);
        float4 xt = make_float4(0.f, 0.f, 0.f, 0.f);
        #pragma unroll
        for (int c = 0; c < CCH; c++) {
            s.x += __expf(v[c].x - m.x); if (c == t.x) xt.x = v[c].x;
            s.y += __expf(v[c].y - m.y); if (c == t.y) xt.y = v[c].y;
            s.z += __expf(v[c].z - m.z); if (c == t.z) xt.z = v[c].z;
            s.w += __expf(v[c].w - m.w); if (c == t.w) xt.w = v[c].w;
        }
        float lpx = xt.x - m.x - __logf(s.x);
        float lpy = xt.y - m.y - __logf(s.y);
        float lpz = xt.z - m.z - __logf(s.z);
        float lpw = xt.w - m.w - __logf(s.w);
        float4 p;
        p.x = (t.x < 0) ? 2.0f : __expf(lpx);
        p.y = (t.y < 0) ? 2.0f : __expf(lpy);
        p.z = (t.z < 0) ? 2.0f : __expf(lpz);
        p.w = (t.w < 0) ? 2.0f : __expf(lpw);

        if (t.x >= 0) { lv++; if (p.x < 0.7f) { ls += -(double)lpx; lc++; } }
        if (t.y >= 0) { lv++; if (p.y < 0.7f) { ls += -(double)lpy; lc++; } }
        if (t.z >= 0) { lv++; if (p.z < 0.7f) { ls += -(double)lpz; lc++; } }
        if (t.w >= 0) { lv++; if (p.w < 0.7f) { ls += -(double)lpw; lc++; } }

        ((float4*)g_prob)[idx] = p;
        atomicAdd(&sh[__float_as_uint(p.x) >> 21], 1u);
        atomicAdd(&sh[__float_as_uint(p.y) >> 21], 1u);
        atomicAdd(&sh[__float_as_uint(p.z) >> 21], 1u);
        atomicAdd(&sh[__float_as_uint(p.w) >> 21], 1u);
    }
    // scalar tail (only if N % 4 != 0)
    if ((N & 3) && blockIdx.x == 0 && threadIdx.x == 0)
        for (int i = N & ~3; i < N; i++) scalar_pixel(predict, target, i, sh, lv, lc, ls);

    __syncthreads();
    for (int i = threadIdx.x; i < NB; i += 256) {
        unsigned v = sh[i];
        if (v) atomicAdd(&g_hist[i], v);
    }
    // block reduce lv, lc, ls
    #pragma unroll
    for (int off = 16; off; off >>= 1) {
        lv += __shfl_down_sync(0xffffffffu, lv, off);
        lc += __shfl_down_sync(0xffffffffu, lc, off);
        ls += __shfl_down_sync(0xffffffffu, ls, off);
    }
    __shared__ int    rv[8], rc[8];
    __shared__ double rs[8];
    int w = threadIdx.x >> 5;
    if ((threadIdx.x & 31) == 0) { rv[w] = lv; rc[w] = lc; rs[w] = ls; }
    __syncthreads();
    if (threadIdx.x == 0) {
        int V = 0, C = 0; double S = 0.0;
        for (int j = 0; j < 8; j++) { V += rv[j]; C += rc[j]; S += rs[j]; }
        if (V) atomicAdd(&g_nvalid, V);
        if (C) atomicAdd(&g_cnt, C);
        if (S != 0.0) atomicAdd(&g_sum, S);
    }
}

// Scan histogram for rank-k bucket; set up band bounds. 256 threads, 1 block.
__global__ void k_scan1(const int* __restrict__ min_kept) {
    __shared__ unsigned ps[256];
    unsigned part = 0;
    for (int j = 0; j < 8; j++) part += g_hist[threadIdx.x * 8 + j];
    ps[threadIdx.x] = part;
    __syncthreads();
    if (threadIdx.x == 0) {
        long long nv = (long long)g_nvalid;
        long long k  = (long long)(*min_kept);
        if (k > nv - 1) k = nv - 1;
        if (k < 0) k = 0;
        long long cum = 0; int chunk = 255;
        for (int c = 0; c < 256; c++) {
            if (cum + (long long)ps[c] > k) { chunk = c; break; }
            cum += ps[c];
        }
        unsigned b = chunk * 8;
        for (int j = 0; j < 8; j++) {
            unsigned h = g_hist[chunk * 8 + j];
            if (cum + (long long)h > k) { b = chunk * 8 + j; break; }
            cum += h;
        }
        unsigned blo = b << 21, bhi = (b + 1) << 21;
        g_blo = blo;
        g_kprime = (int)(k - cum);
        if (bhi > T7BITS) { g_band = 1; g_tmax = bhi; }
        else              { g_band = 0; g_thresh = T7BITS; }  // threshold = 0.7, done
    }
    __syncthreads();
    for (int j = threadIdx.x; j < NB; j += 256) g_hist[j] = 0u;
}

// Band pass (only if 0.7 < bucket_hi): compact candidates [0.7, bucket_hi),
// count elements in [bucket_lo, 0.7).
__global__ void k_select(int N) {
    if (!g_band) return;
    unsigned tmax = g_tmax, blo = g_blo;
    int N4 = N >> 2;
    int T = gridDim.x * blockDim.x;
    int gtid = blockIdx.x * blockDim.x + threadIdx.x;
    int iters = (N4 + T - 1) / T;
    int lclow = 0;
    int lane = threadIdx.x & 31;
    for (int it = 0; it < iters; it++) {
        int idx = it * T + gtid;
        bool active = idx < N4;
        float4 p = active ? ((const float4*)g_prob)[idx] : make_float4(0.f, 0.f, 0.f, 0.f);
        unsigned u4[4] = {__float_as_uint(p.x), __float_as_uint(p.y),
                          __float_as_uint(p.z), __float_as_uint(p.w)};
        #pragma unroll
        for (int j = 0; j < 4; j++) {
            unsigned u = u4[j];
            bool cand = active && u >= T7BITS && u < tmax;
            unsigned mask = __ballot_sync(0xffffffffu, cand);
            if (mask) {
                int leader = __ffs(mask) - 1;
                int pos = 0;
                if (lane == leader) pos = atomicAdd(&g_ncand, __popc(mask));
                pos = __shfl_sync(0xffffffffu, pos, leader);
                if (cand) g_cand[pos + __popc(mask & ((1u << lane) - 1u))] = u;
            }
            if (active && u >= blo && u < T7BITS) lclow++;
        }
    }
    if ((N & 3) && blockIdx.x == 0 && threadIdx.x == 0)
        for (int i = N & ~3; i < N; i++) {
            unsigned u = __float_as_uint(g_prob[i]);
            if (u >= T7BITS && u < tmax) { int pos = atomicAdd(&g_ncand, 1); g_cand[pos] = u; }
            if (u >= blo && u < T7BITS) lclow++;
        }
    #pragma unroll
    for (int off = 16; off; off >>= 1) lclow += __shfl_down_sync(0xffffffffu, lclow, off);
    if (lane == 0 && lclow) atomicAdd(&g_cntlow, lclow);
}

// Refine level 1: histogram bits[10:21) of candidates within the kth bucket.
__global__ void k_refine1() {
    __shared__ unsigned sh[NB];
    for (int i = threadIdx.x; i < NB; i += blockDim.x) sh[i] = 0u;
    __syncthreads();
    int n = g_ncand;
    unsigned btop = g_blo >> 21;
    for (int i = blockIdx.x * blockDim.x + threadIdx.x; i < n; i += gridDim.x * blockDim.x) {
        unsigned u = g_cand[i];
        if ((u >> 21) == btop) atomicAdd(&sh[(u >> 10) & 2047u], 1u);
    }
    __syncthreads();
    for (int i = threadIdx.x; i < NB; i += blockDim.x) {
        unsigned v = sh[i];
        if (v) atomicAdd(&g_hist[i], v);
    }
}

__global__ void k_scanr1() {
    __shared__ unsigned ps[256];
    unsigned part = 0;
    for (int j = 0; j < 8; j++) part += g_hist[threadIdx.x * 8 + j];
    ps[threadIdx.x] = part;
    __syncthreads();
    if (threadIdx.x == 0) {
        if (g_band) {
            long long kb = (long long)g_kprime - (long long)g_cntlow;
            if (kb < 0) { g_thresh = T7BITS; g_b2 = 0xFFFFFFFFu; }
            else {
                long long cum = 0; int chunk = 255;
                for (int c = 0; c < 256; c++) {
                    if (cum + (long long)ps[c] > kb) { chunk = c; break; }
                    cum += ps[c];
                }
                unsigned b2 = chunk * 8;
                for (int j = 0; j < 8; j++) {
                    unsigned h = g_hist[chunk * 8 + j];
                    if (cum + (long long)h > kb) { b2 = chunk * 8 + j; break; }
                    cum += h;
                }
                g_b2 = b2;
                g_k3 = (int)(kb - cum);
            }
        }
    }
    __syncthreads();
    for (int j = threadIdx.x; j < NB; j += 256) g_hist[j] = 0u;
}

// Refine level 2: histogram bits[0:10) within chosen sub-bucket.
__global__ void k_refine2() {
    __shared__ unsigned sh[1024];
    for (int i = threadIdx.x; i < 1024; i += blockDim.x) sh[i] = 0u;
    __syncthreads();
    int n = g_ncand;
    unsigned btop = g_blo >> 21, b2 = g_b2;
    for (int i = blockIdx.x * blockDim.x + threadIdx.x; i < n; i += gridDim.x * blockDim.x) {
        unsigned u = g_cand[i];
        if ((u >> 21) == btop && ((u >> 10) & 2047u) == b2) atomicAdd(&sh[u & 1023u], 1u);
    }
    __syncthreads();
    for (int i = threadIdx.x; i < 1024; i += blockDim.x) {
        unsigned v = sh[i];
        if (v) atomicAdd(&g_hist[i], v);
    }
}

__global__ void k_scanr2() {
    __shared__ unsigned ps[256];
    unsigned part = 0;
    for (int j = 0; j < 4; j++) part += g_hist[threadIdx.x * 4 + j];
    ps[threadIdx.x] = part;
    __syncthreads();
    if (threadIdx.x == 0 && g_b2 != 0xFFFFFFFFu) {
        long long k = (long long)g_k3;
        long long cum = 0; int chunk = 255;
        for (int c = 0; c < 256; c++) {
            if (cum + (long long)ps[c] > k) { chunk = c; break; }
            cum += ps[c];
        }
        unsigned b3 = chunk * 4;
        for (int j = 0; j < 4; j++) {
            unsigned h = g_hist[chunk * 4 + j];
            if (cum + (long long)h > k) { b3 = chunk * 4 + j; break; }
            cum += h;
        }
        g_thresh = g_blo | (g_b2 << 10) | b3;   // exact kth bit pattern (>= 0.7)
    }
}

// Sum candidates below threshold (band contribution; usually empty).
__global__ void k_band_sum() {
    int n = g_ncand;
    unsigned th = g_thresh;
    double s = 0.0; int c = 0;
    for (int i = blockIdx.x * blockDim.x + threadIdx.x; i < n; i += gridDim.x * blockDim.x) {
        unsigned u = g_cand[i];
        if (u < th) { s += -(double)__logf(__uint_as_float(u)); c++; }
    }
    #pragma unroll
    for (int off = 16; off; off >>= 1) {
        s += __shfl_down_sync(0xffffffffu, s, off);
        c += __shfl_down_sync(0xffffffffu, c, off);
    }
    __shared__ double rs[8];
    __shared__ int    rc[8];
    int w = threadIdx.x >> 5;
    if ((threadIdx.x & 31) == 0) { rs[w] = s; rc[w] = c; }
    __syncthreads();
    if (threadIdx.x == 0) {
        double S = 0.0; int C = 0;
        int nw = (blockDim.x + 31) >> 5;
        for (int j = 0; j < nw; j++) { S += rs[j]; C += rc[j]; }
        if (C) { atomicAdd(&g_sum, S); atomicAdd(&g_cnt, C); }
    }
}

__global__ void k_final(float* out) {
    int c = g_cnt;
    if (c < 1) c = 1;
    out[0] = (float)(g_sum / (double)c);
}

// ---------------------------------------------------------------
extern "C" void kernel_launch(void* const* d_in, const int* in_sizes, int n_in,
                              void* d_out, int out_size) {
    const float* predict  = (const float*)d_in[0];
    const int*   target   = (const int*)d_in[1];
    const int*   min_kept = (const int*)d_in[2];
    float*       out      = (float*)d_out;

    int N = in_sizes[1];
    int N4 = N >> 2;
    int grid = (N4 + 255) / 256;   // 2048 for this shape

    k_init    <<<1, 256>>>();
    k_compute <<<grid, 256>>>(predict, target, N);
    k_scan1   <<<1, 256>>>(min_kept);
    k_select  <<<grid, 256>>>(N);
    k_refine1 <<<148, 256>>>();
    k_scanr1  <<<1, 256>>>();
    k_refine2 <<<148, 256>>>();
    k_scanr2  <<<1, 256>>>();
    k_band_sum<<<148, 256>>>();
    k_final   <<<1, 1>>>(out);
}

// round 3
// speedup vs baseline: 2.9605x; 1.2646x over previous
#include <cuda_runtime.h>
#include <math.h>

// predict (8,19,512,512) f32, target (8,512,512) i32, min_kept (1) i32 -> scalar f32
#define NPIX    (8 * 512 * 512)
#define HWSZ    (512 * 512)
#define CCH     19
#define NB      2048
#define T7BITS  0x3F333333u          // bits of 0.7f
#define CANDMIN (T7BITS - (1u << 21)) // lowest possible blo of a band-active bucket
#define ONEBITS 0x3F800000u          // bits of 1.0f

// ---------------- device scratch ----------------
__device__ unsigned int g_cand[NPIX];   // compacted candidate bit patterns (u in [CANDMIN, 1.0])
__device__ unsigned int g_hist[NB];
__device__ int          g_nvalid, g_ncand, g_cnt;
__device__ double       g_sum;
__device__ unsigned int g_blo, g_thresh;
__device__ int          g_kprime, g_band;

// ---------------------------------------------------------------
__global__ void k_init() {
    for (int i = threadIdx.x; i < NB; i += blockDim.x) g_hist[i] = 0u;
    if (threadIdx.x == 0) {
        g_nvalid = 0; g_ncand = 0; g_cnt = 0;
        g_sum = 0.0; g_band = 0; g_thresh = T7BITS;
    }
}

// Pass A: online softmax prob of target class, top-11-bit histogram, valid count,
// sure-selected (p < 0.7) loss sum, and compaction of possible-band candidates.
__global__ void __launch_bounds__(256, 2)
k_compute(const float* __restrict__ predict, const int* __restrict__ target, int N) {
    __shared__ unsigned sh[NB];
    for (int i = threadIdx.x; i < NB; i += 256) sh[i] = 0u;
    __syncthreads();

    int N4 = N >> 2;
    int idx = blockIdx.x * 256 + threadIdx.x;
    int lv = 0, lc = 0;
    double ls = 0.0;
    int lane = threadIdx.x & 31;

    if (idx < N4) {
        int i = idx << 2;
        int n = i / HWSZ, hw = i - n * HWSZ;
        const float4* base = (const float4*)(predict + (size_t)n * CCH * HWSZ + hw);
        float4 v[CCH];
        #pragma unroll
        for (int c = 0; c < CCH; c++) v[c] = __ldg(base + (size_t)c * (HWSZ / 4));
        int4 t = *(const int4*)(target + i);

        float4 m = v[0];
        #pragma unroll
        for (int c = 1; c < CCH; c++) {
            m.x = fmaxf(m.x, v[c].x); m.y = fmaxf(m.y, v[c].y);
            m.z = fmaxf(m.z, v[c].z); m.w = fmaxf(m.w, v[c].w);
        }
        float4 s = make_float4(0.f, 0.f, 0.f, 0.f);
        float4 xt = make_float4(0.f, 0.f, 0.f, 0.f);
        #pragma unroll
        for (int c = 0; c < CCH; c++) {
            s.x += __expf(v[c].x - m.x); if (c == t.x) xt.x = v[c].x;
            s.y += __expf(v[c].y - m.y); if (c == t.y) xt.y = v[c].y;
            s.z += __expf(v[c].z - m.z); if (c == t.z) xt.z = v[c].z;
            s.w += __expf(v[c].w - m.w); if (c == t.w) xt.w = v[c].w;
        }
        float lp[4];
        lp[0] = xt.x - m.x - __logf(s.x);
        lp[1] = xt.y - m.y - __logf(s.y);
        lp[2] = xt.z - m.z - __logf(s.z);
        lp[3] = xt.w - m.w - __logf(s.w);
        int tt[4] = {t.x, t.y, t.z, t.w};
        unsigned u[4];
        #pragma unroll
        for (int j = 0; j < 4; j++) {
            float p = (tt[j] < 0) ? 2.0f : __expf(lp[j]);
            u[j] = __float_as_uint(p);
            if (tt[j] >= 0) {
                lv++;
                if (p < 0.7f) { ls += -(double)lp[j]; lc++; }
            }
            atomicAdd(&sh[u[j] >> 21], 1u);
        }
        // compact potential band candidates (valid probs in [CANDMIN, 1.0])
        #pragma unroll
        for (int j = 0; j < 4; j++) {
            bool cand = (tt[j] >= 0) && (u[j] >= CANDMIN) && (u[j] <= ONEBITS);
            unsigned mask = __ballot_sync(0xffffffffu, cand);
            if (mask) {
                int leader = __ffs(mask) - 1;
                int pos = 0;
                if (lane == leader) pos = atomicAdd(&g_ncand, __popc(mask));
                pos = __shfl_sync(0xffffffffu, pos, leader);
                if (cand) g_cand[pos + __popc(mask & ((1u << lane) - 1u))] = u[j];
            }
        }
    } else {
        // keep warp-uniform ballots for the (non-existent here) partial warp case
        #pragma unroll
        for (int j = 0; j < 4; j++) (void)__ballot_sync(0xffffffffu, false);
    }

    // scalar tail (N % 4 != 0; not hit for this shape)
    if ((N & 3) && blockIdx.x == 0 && threadIdx.x == 0) {
        for (int i = N & ~3; i < N; i++) {
            int t0 = target[i];
            float p;
            if (t0 < 0) p = 2.0f;
            else {
                int n = i / HWSZ, hw = i - n * HWSZ;
                const float* b2 = predict + (size_t)n * CCH * HWSZ + hw;
                float mm = -1e30f;
                for (int c = 0; c < CCH; c++) mm = fmaxf(mm, __ldg(b2 + (size_t)c * HWSZ));
                float ss = 0.0f, xt0 = 0.0f;
                for (int c = 0; c < CCH; c++) {
                    float x = __ldg(b2 + (size_t)c * HWSZ);
                    ss += __expf(x - mm);
                    if (c == t0) xt0 = x;
                }
                float l0 = xt0 - mm - __logf(ss);
                p = __expf(l0);
                lv++;
                if (p < 0.7f) { ls += -(double)l0; lc++; }
            }
            unsigned uu = __float_as_uint(p);
            atomicAdd(&sh[uu >> 21], 1u);
            if (t0 >= 0 && uu >= CANDMIN && uu <= ONEBITS) {
                int pos = atomicAdd(&g_ncand, 1);
                g_cand[pos] = uu;
            }
        }
    }

    __syncthreads();
    for (int i = threadIdx.x; i < NB; i += 256) {
        unsigned h = sh[i];
        if (h) atomicAdd(&g_hist[i], h);
    }
    #pragma unroll
    for (int off = 16; off; off >>= 1) {
        lv += __shfl_down_sync(0xffffffffu, lv, off);
        lc += __shfl_down_sync(0xffffffffu, lc, off);
        ls += __shfl_down_sync(0xffffffffu, ls, off);
    }
    __shared__ int    rv[8], rc[8];
    __shared__ double rs[8];
    int w = threadIdx.x >> 5;
    if (lane == 0) { rv[w] = lv; rc[w] = lc; rs[w] = ls; }
    __syncthreads();
    if (threadIdx.x == 0) {
        int V = 0, C = 0; double S = 0.0;
        for (int j = 0; j < 8; j++) { V += rv[j]; C += rc[j]; S += rs[j]; }
        if (V) atomicAdd(&g_nvalid, V);
        if (C) atomicAdd(&g_cnt, C);
        if (S != 0.0) atomicAdd(&g_sum, S);
    }
}

// Pick the rank-k top-11-bit bucket. Single block.
__global__ void k_scan1(const int* __restrict__ min_kept) {
    __shared__ unsigned ps[256];
    unsigned part = 0;
    for (int j = 0; j < 8; j++) part += g_hist[threadIdx.x * 8 + j];
    ps[threadIdx.x] = part;
    __syncthreads();
    if (threadIdx.x == 0) {
        long long nv = (long long)g_nvalid;
        long long k  = (long long)(*min_kept);
        if (k > nv - 1) k = nv - 1;
        if (k < 0) k = 0;
        long long cum = 0; int chunk = 255;
        for (int c = 0; c < 256; c++) {
            if (cum + (long long)ps[c] > k) { chunk = c; break; }
            cum += ps[c];
        }
        unsigned b = chunk * 8;
        for (int j = 0; j < 8; j++) {
            unsigned h = g_hist[chunk * 8 + j];
            if (cum + (long long)h > k) { b = chunk * 8 + j; break; }
            cum += h;
        }
        unsigned blo = b << 21, bhi = (b + 1) << 21;
        g_blo = blo;
        g_kprime = (int)(k - cum);
        g_band = (bhi > T7BITS) ? 1 : 0;   // else threshold = 0.7, already final
    }
}

// Full band refinement in ONE block (only runs when bucket_hi > 0.7).
// Finds exact kth bit pattern among candidates, then adds the [0.7, thresh) band
// contribution to the loss sum. Candidates in g_cand cover the whole kth bucket
// because blo >= CANDMIN whenever the band is active.
__global__ void k_band() {
    if (g_band == 0) return;
    __shared__ unsigned hist[NB];
    __shared__ int      s_low;
    __shared__ unsigned s_b2, s_done;
    int n = g_ncand;
    unsigned btop = g_blo >> 21;

    // ---- phase 1: cntlow + histogram bits[10:21) of bucket ∩ [0.7, bhi) ----
    for (int i = threadIdx.x; i < NB; i += blockDim.x) hist[i] = 0u;
    if (threadIdx.x == 0) { s_low = 0; s_done = 0; }
    __syncthreads();
    int lclow = 0;
    for (int i = threadIdx.x; i < n; i += blockDim.x) {
        unsigned u = g_cand[i];
        if ((u >> 21) == btop) {
            if (u < T7BITS) lclow++;
            else atomicAdd(&hist[(u >> 10) & 2047u], 1u);
        }
    }
    if (lclow) atomicAdd(&s_low, lclow);
    __syncthreads();

    if (threadIdx.x == 0) {
        long long kb = (long long)g_kprime - (long long)s_low;
        if (kb < 0) { g_thresh = T7BITS; s_done = 1; }
        else {
            long long cum = 0; unsigned b2 = 2047;
            for (unsigned i = 0; i < NB; i++) {
                unsigned h = hist[i];
                if (cum + (long long)h > kb) { b2 = i; break; }
                cum += h;
            }
            s_b2 = b2;
            g_kprime = (int)(kb - cum);   // reuse as rank within sub-bucket
        }
    }
    __syncthreads();
    if (s_done) return;                   // threshold stays 0.7 -> band empty

    // ---- phase 2: histogram bits[0:10) within chosen sub-bucket ----
    unsigned pref = (btop << 11) | s_b2;
    for (int i = threadIdx.x; i < 1024; i += blockDim.x) hist[i] = 0u;
    __syncthreads();
    for (int i = threadIdx.x; i < n; i += blockDim.x) {
        unsigned u = g_cand[i];
        if ((u >> 10) == pref && u >= T7BITS) atomicAdd(&hist[u & 1023u], 1u);
    }
    __syncthreads();
    if (threadIdx.x == 0) {
        long long k = (long long)g_kprime;
        long long cum = 0; unsigned b3 = 1023;
        for (unsigned i = 0; i < 1024; i++) {
            unsigned h = hist[i];
            if (cum + (long long)h > k) { b3 = i; break; }
            cum += h;
        }
        g_thresh = (pref << 10) | b3;     // exact kth bit pattern (> 0.7 here)
    }
    __syncthreads();

    // ---- phase 3: add band contribution: 0.7 <= p < thresh ----
    unsigned th = g_thresh;
    double s = 0.0; int c = 0;
    for (int i = threadIdx.x; i < n; i += blockDim.x) {
        unsigned u = g_cand[i];
        if (u >= T7BITS && u < th) { s += -(double)__logf(__uint_as_float(u)); c++; }
    }
    #pragma unroll
    for (int off = 16; off; off >>= 1) {
        s += __shfl_down_sync(0xffffffffu, s, off);
        c += __shfl_down_sync(0xffffffffu, c, off);
    }
    __shared__ double rs[32];
    __shared__ int    rc[32];
    int w = threadIdx.x >> 5;
    if ((threadIdx.x & 31) == 0) { rs[w] = s; rc[w] = c; }
    __syncthreads();
    if (threadIdx.x == 0) {
        double S = 0.0; int C = 0;
        int nw = (blockDim.x + 31) >> 5;
        for (int j = 0; j < nw; j++) { S += rs[j]; C += rc[j]; }
        if (C) { atomicAdd(&g_sum, S); atomicAdd(&g_cnt, C); }
    }
}

__global__ void k_final(float* out) {
    int c = g_cnt;
    if (c < 1) c = 1;
    out[0] = (float)(g_sum / (double)c);
}

// ---------------------------------------------------------------
extern "C" void kernel_launch(void* const* d_in, const int* in_sizes, int n_in,
                              void* d_out, int out_size) {
    const float* predict  = (const float*)d_in[0];
    const int*   target   = (const int*)d_in[1];
    const int*   min_kept = (const int*)d_in[2];
    float*       out      = (float*)d_out;

    int N = in_sizes[1];
    int N4 = N >> 2;
    int grid = (N4 + 255) / 256;   // 2048 for this shape

    k_init    <<<1, 256>>>();
    k_compute <<<grid, 256>>>(predict, target, N);
    k_scan1   <<<1, 256>>>(min_kept);
    k_band    <<<1, 1024>>>();
    k_final   <<<1, 1>>>(out);
}

// round 4
// speedup vs baseline: 3.5341x; 1.1938x over previous
#include <cuda_runtime.h>
#include <math.h>

// predict (8,19,512,512) f32, target (8,512,512) i32, min_kept (1) i32 -> scalar f32
#define NPIX    (8 * 512 * 512)
#define HWSZ    (512 * 512)
#define CCH     19
#define T7BITS  0x3F333333u     // bits of 0.7f
#define MAXBLK  4096

// ---------------- device scratch ----------------
__device__ unsigned int g_cand[NPIX];   // candidates: valid probs with p >= 0.7 (bit patterns)
__device__ int          g_ncand = 0;    // reset to 0 by k_finalize each run
__device__ int          g_plv[MAXBLK];  // per-block valid count
__device__ int          g_plc[MAXBLK];  // per-block count of (valid && p < 0.7)
__device__ double       g_pls[MAXBLK];  // per-block sum of -log p over (valid && p < 0.7)

// ---------------------------------------------------------------
// Pass A: softmax prob of target class; accumulate sure-selected (p<0.7) loss;
// compact p>=0.7 candidates. Per-block partials, no global atomics except cand.
__global__ void __launch_bounds__(256, 2)
k_compute(const float* __restrict__ predict, const int* __restrict__ target, int N) {
    int N4 = N >> 2;
    int idx = blockIdx.x * 256 + threadIdx.x;
    int lv = 0, lc = 0;
    double ls = 0.0;
    int lane = threadIdx.x & 31;

    if (idx < N4) {
        int i = idx << 2;
        int n = i / HWSZ, hw = i - n * HWSZ;
        const float4* base = (const float4*)(predict + (size_t)n * CCH * HWSZ + hw);
        float4 v[CCH];
        #pragma unroll
        for (int c = 0; c < CCH; c++) v[c] = __ldg(base + (size_t)c * (HWSZ / 4));
        int4 t = *(const int4*)(target + i);

        float4 m = v[0];
        #pragma unroll
        for (int c = 1; c < CCH; c++) {
            m.x = fmaxf(m.x, v[c].x); m.y = fmaxf(m.y, v[c].y);
            m.z = fmaxf(m.z, v[c].z); m.w = fmaxf(m.w, v[c].w);
        }
        float4 s = make_float4(0.f, 0.f, 0.f, 0.f);
        float4 xt = make_float4(0.f, 0.f, 0.f, 0.f);
        #pragma unroll
        for (int c = 0; c < CCH; c++) {
            s.x += __expf(v[c].x - m.x); if (c == t.x) xt.x = v[c].x;
            s.y += __expf(v[c].y - m.y); if (c == t.y) xt.y = v[c].y;
            s.z += __expf(v[c].z - m.z); if (c == t.z) xt.z = v[c].z;
            s.w += __expf(v[c].w - m.w); if (c == t.w) xt.w = v[c].w;
        }
        float lp[4];
        lp[0] = xt.x - m.x - __logf(s.x);
        lp[1] = xt.y - m.y - __logf(s.y);
        lp[2] = xt.z - m.z - __logf(s.z);
        lp[3] = xt.w - m.w - __logf(s.w);
        int tt[4] = {t.x, t.y, t.z, t.w};
        #pragma unroll
        for (int j = 0; j < 4; j++) {
            bool valid = (tt[j] >= 0);
            float p = valid ? __expf(lp[j]) : 2.0f;
            unsigned u = __float_as_uint(p);
            if (valid) {
                lv++;
                if (p < 0.7f) { ls += -(double)lp[j]; lc++; }
            }
            // warp-aggregated push of p >= 0.7 candidates (rare)
            bool cand = valid && (u >= T7BITS);
            unsigned mask = __ballot_sync(0xffffffffu, cand);
            if (mask) {
                int leader = __ffs(mask) - 1;
                int pos = 0;
                if (lane == leader) pos = atomicAdd(&g_ncand, __popc(mask));
                pos = __shfl_sync(0xffffffffu, pos, leader);
                if (cand) g_cand[pos + __popc(mask & ((1u << lane) - 1u))] = u;
            }
        }
    } else {
        #pragma unroll
        for (int j = 0; j < 4; j++) (void)__ballot_sync(0xffffffffu, false);
    }

    // scalar tail (N % 4 != 0; not hit for this shape)
    if ((N & 3) && blockIdx.x == 0 && threadIdx.x == 0) {
        for (int i = N & ~3; i < N; i++) {
            int t0 = target[i];
            if (t0 < 0) continue;
            int n = i / HWSZ, hw = i - n * HWSZ;
            const float* b2 = predict + (size_t)n * CCH * HWSZ + hw;
            float mm = -1e30f;
            for (int c = 0; c < CCH; c++) mm = fmaxf(mm, __ldg(b2 + (size_t)c * HWSZ));
            float ss = 0.0f, xt0 = 0.0f;
            for (int c = 0; c < CCH; c++) {
                float x = __ldg(b2 + (size_t)c * HWSZ);
                ss += __expf(x - mm);
                if (c == t0) xt0 = x;
            }
            float l0 = xt0 - mm - __logf(ss);
            float p = __expf(l0);
            lv++;
            if (p < 0.7f) { ls += -(double)l0; lc++; }
            else {
                int pos = atomicAdd(&g_ncand, 1);
                g_cand[pos] = __float_as_uint(p);
            }
        }
    }

    // block-level reduction -> per-block partials (no init needed, no atomics)
    #pragma unroll
    for (int off = 16; off; off >>= 1) {
        lv += __shfl_down_sync(0xffffffffu, lv, off);
        lc += __shfl_down_sync(0xffffffffu, lc, off);
        ls += __shfl_down_sync(0xffffffffu, ls, off);
    }
    __shared__ int    rv[8], rc[8];
    __shared__ double rs[8];
    int w = threadIdx.x >> 5;
    if (lane == 0) { rv[w] = lv; rc[w] = lc; rs[w] = ls; }
    __syncthreads();
    if (threadIdx.x == 0) {
        int V = 0, C = 0; double S = 0.0;
        #pragma unroll
        for (int j = 0; j < 8; j++) { V += rv[j]; C += rc[j]; S += rs[j]; }
        g_plv[blockIdx.x] = V;
        g_plc[blockIdx.x] = C;
        g_pls[blockIdx.x] = S;
    }
}

// ---------------------------------------------------------------
// Single block: reduce partials; decide threshold; (rarely) radix-select the
// exact kth value among p>=0.7 candidates; write result; reset g_ncand.
__global__ void __launch_bounds__(1024, 1)
k_finalize(const int* __restrict__ min_kept, float* __restrict__ out, int nblk) {
    __shared__ unsigned hist[4096];      // 16 KB, reused across passes
    __shared__ int    rv[32], rc[32];
    __shared__ double rs[32];
    __shared__ long long sV, sC;
    __shared__ double sS;
    __shared__ int s_mode;               // 0 = threshold 0.7 (done), 1 = band select
    __shared__ long long s_r;            // rank among candidates
    __shared__ unsigned s_b1, s_th;

    int tid = threadIdx.x;
    int lane = tid & 31, w = tid >> 5;

    // ---- reduce per-block partials ----
    long long lv = 0, lc = 0; double ls = 0.0;
    for (int i = tid; i < nblk; i += 1024) {
        lv += g_plv[i]; lc += g_plc[i]; ls += g_pls[i];
    }
    #pragma unroll
    for (int off = 16; off; off >>= 1) {
        lv += __shfl_down_sync(0xffffffffu, lv, off);
        lc += __shfl_down_sync(0xffffffffu, lc, off);
        ls += __shfl_down_sync(0xffffffffu, ls, off);
    }
    if (lane == 0) { rv[w] = (int)lv; rc[w] = (int)lc; rs[w] = ls; }
    __syncthreads();
    if (tid == 0) {
        long long V = 0, C = 0; double S = 0.0;
        for (int j = 0; j < 32; j++) { V += rv[j]; C += rc[j]; S += rs[j]; }
        sV = V; sC = C; sS = S;
        long long k = (long long)(*min_kept);
        if (k > V - 1) k = V - 1;
        if (k < 0) k = 0;
        if (V == 0 || C >= k + 1) s_mode = 0;     // threshold = 0.7; answer is S/C
        else { s_mode = 1; s_r = k - C; }          // kth is rank (k-C) among candidates
    }
    __syncthreads();

    if (s_mode == 1) {
        // ---- exact kth among candidates via 2-pass radix on key = u - T7BITS ----
        int n = g_ncand;
        // pass 1: bits [12:23) of 23-bit key
        for (int i = tid; i < 4096; i += 1024) hist[i] = 0u;
        __syncthreads();
        for (int i = tid; i < n; i += 1024) {
            unsigned key = g_cand[i] - T7BITS;
            atomicAdd(&hist[key >> 12], 1u);
        }
        __syncthreads();
        if (tid == 0) {
            long long r = s_r, cum = 0; unsigned b1 = 2047;
            for (unsigned i = 0; i < 2048; i++) {
                unsigned h = hist[i];
                if (cum + (long long)h > r) { b1 = i; break; }
                cum += h;
            }
            s_b1 = b1; s_r = r - cum;
        }
        __syncthreads();
        // pass 2: bits [0:12) within chosen bucket
        unsigned b1 = s_b1;
        for (int i = tid; i < 4096; i += 1024) hist[i] = 0u;
        __syncthreads();
        for (int i = tid; i < n; i += 1024) {
            unsigned key = g_cand[i] - T7BITS;
            if ((key >> 12) == b1) atomicAdd(&hist[key & 4095u], 1u);
        }
        __syncthreads();
        if (tid == 0) {
            long long r = s_r, cum = 0; unsigned b2 = 4095;
            for (unsigned i = 0; i < 4096; i++) {
                unsigned h = hist[i];
                if (cum + (long long)h > r) { b2 = i; break; }
                cum += h;
            }
            s_th = T7BITS + ((b1 << 12) | b2);   // exact kth bit pattern (>= 0.7)
        }
        __syncthreads();
        // band contribution: candidates with u < kth
        unsigned th = s_th;
        double bs = 0.0; long long bc = 0;
        for (int i = tid; i < n; i += 1024) {
            unsigned u = g_cand[i];
            if (u < th) { bs += -(double)__logf(__uint_as_float(u)); bc++; }
        }
        #pragma unroll
        for (int off = 16; off; off >>= 1) {
            bs += __shfl_down_sync(0xffffffffu, bs, off);
            bc += __shfl_down_sync(0xffffffffu, bc, off);
        }
        if (lane == 0) { rs[w] = bs; rc[w] = (int)bc; }
        __syncthreads();
        if (tid == 0) {
            double S2 = 0.0; long long C2 = 0;
            for (int j = 0; j < 32; j++) { S2 += rs[j]; C2 += rc[j]; }
            sS += S2; sC += C2;
        }
        __syncthreads();
    }

    if (tid == 0) {
        long long C = sC;
        double den = (C < 1) ? 1.0 : (double)C;
        out[0] = (sV == 0) ? 0.0f : (float)(sS / den);
        g_ncand = 0;                     // reset for next graph replay
    }
}

// ---------------------------------------------------------------
extern "C" void kernel_launch(void* const* d_in, const int* in_sizes, int n_in,
                              void* d_out, int out_size) {
    const float* predict  = (const float*)d_in[0];
    const int*   target   = (const int*)d_in[1];
    const int*   min_kept = (const int*)d_in[2];
    float*       out      = (float*)d_out;

    int N = in_sizes[1];
    int N4 = N >> 2;
    int grid = (N4 + 255) / 256;     // 2048 for this shape (<= MAXBLK)

    k_compute <<<grid, 256>>>(predict, target, N);
    k_finalize<<<1, 1024>>>(min_kept, out, grid);
}